// round 7
// baseline (speedup 1.0000x reference)
#include <cuda_runtime.h>

// Problem shape (fixed by setup_inputs): x: (B=4, S=4096, D=64) f32; out: (B,S) f32
#define S_LEN  4096
#define D_DIM  64
#define CH     8               // chunk size (norm elements per L1 entry)
#define NCH    (S_LEN / CH)    // 512 chunks per row
#define NB     128             // grid (co-resident: 128 <= 148 SMs, 1 block/SM)
#define NT     512             // threads per block
#define QPB    128             // queries per block (32 blocks per batch row)

// Device-global scratch (no allocation):
__device__ float    g_norms[4 * S_LEN];
__device__ unsigned g_bar;     // monotonic grid-barrier counter (each launch
                               // adds exactly NB; generation inferred, no reset)

// Max m in [0,7] s.t. windows [pos-k*s, pos-(k-1)*s) are all clean for k<=m.
// tab[c] = min over s chunks starting at c. The 7 loads are independent.
__device__ __forceinline__ int leading_clean7(const float* __restrict__ tab,
                                              int pos, int s, float thr) {
    bool ok = true;
    int m = 0;
#pragma unroll
    for (int k = 1; k <= 7; k++) {
        const int npos = pos - k * s;
        const float v = tab[npos >= 0 ? npos : 0];
        ok = ok && (npos >= 0) && (v >= thr);
        m += ok ? 1 : 0;
    }
    return m;
}

__device__ __forceinline__ float abs4(float4 v) {
    return fabsf(v.x) + fabsf(v.y) + fabsf(v.z) + fabsf(v.w);
}
__device__ __forceinline__ float min8(float4 a, float4 b) {
    return fminf(fminf(fminf(a.x, a.y), fminf(a.z, a.w)),
                 fminf(fminf(b.x, b.y), fminf(b.z, b.w)));
}

__global__ void __launch_bounds__(NT, 1) fused_kernel(const float* __restrict__ x,
                                                      float* __restrict__ out) {
    __shared__ float sn[S_LEN];      // 16 KB norms row
    __shared__ float sL1[NCH];       // 2 KB: min over 1 chunk  (8 elems)
    __shared__ float sL8[NCH];       // 2 KB: min over 8 chunks
    __shared__ float sL64[NCH];      // 2 KB: min over 64 chunks

    const int tid = threadIdx.x;

    // ---------- Phase 1: norms. 4 threads per row, one pass. ----------
    // 65536 threads, 16384 rows. Thread reads 16 contiguous floats (4x float4,
    // issued back-to-back -> MLP=4); warp covers 2KB contiguous (coalesced).
    {
        const int gtid = blockIdx.x * NT + tid;
        const int row  = gtid >> 2;
        const int q    = gtid & 3;
        const float4* src = reinterpret_cast<const float4*>(x + (size_t)row * D_DIM) + q * 4;
        const float4 a0 = src[0];
        const float4 a1 = src[1];
        const float4 a2 = src[2];
        const float4 a3 = src[3];
        float s = (abs4(a0) + abs4(a1)) + (abs4(a2) + abs4(a3));
        s += __shfl_xor_sync(0xffffffffu, s, 1);
        s += __shfl_xor_sync(0xffffffffu, s, 2);
        if (q == 0) g_norms[row] = s;
    }

    // ---------- Grid barrier (monotonic counter, volatile poll) ----------
    __threadfence();             // publish g_norms
    __syncthreads();             // whole block arrived
    if (tid == 0) {
        const unsigned my = atomicAdd(&g_bar, 1u) + 1u;
        const unsigned target = (my + NB - 1u) / NB * NB;   // end of this generation
        volatile unsigned* p = &g_bar;
        while (*p < target) { }
        __threadfence();
    }
    __syncthreads();

    // ---------- Phase 2: stage row + build tables (1 chunk per thread) -----
    const int b     = blockIdx.x >> 5;            // 32 blocks per batch row
    const int tbase = (blockIdx.x & 31) * QPB;

    {
        const float4* srcN = reinterpret_cast<const float4*>(g_norms + (size_t)b * S_LEN);
        const float4 a0 = srcN[2 * tid + 0];      // chunk tid = floats [8t, 8t+8)
        const float4 a1 = srcN[2 * tid + 1];
        float4* dst = reinterpret_cast<float4*>(sn);
        dst[2 * tid + 0] = a0;
        dst[2 * tid + 1] = a1;
        sL1[tid] = min8(a0, a1);
    }
    __syncthreads();

    // L8[c] = min over L1[c .. c+7] (clamped tail reads are harmless).
    {
        float m = sL1[tid];
#pragma unroll
        for (int k = 1; k < 8; k++) {
            const int idx = tid + k;
            m = fminf(m, sL1[idx < NCH ? idx : NCH - 1]);
        }
        sL8[tid] = m;
    }
    __syncthreads();

    // L64[c] = min over 64 chunks = 8 L8 entries at stride 8.
    {
        float m = sL8[tid];
#pragma unroll
        for (int k = 1; k < 8; k++) {
            const int idx = tid + k * 8;
            m = fminf(m, sL8[idx < NCH ? idx : NCH - 1]);
        }
        sL64[tid] = m;
    }
    __syncthreads();

    // ---------- Phase 3: one query per thread (tid < QPB) ----------
    if (tid < QPB) {
        const int t = tbase + tid;
        const float thr = 0.7f * (sn[t] + 1e-8f);

        // A) partial chunk [cb, t): predicated scan, ascending keeps max j.
        const int cb = t & ~(CH - 1);
        int best = -1;
#pragma unroll
        for (int k = 0; k < CH - 1; k++) {
            const int j = cb + k;
            if (j < t && sn[j] < thr) best = j;
        }

        // B) 7-ary descend over scales {64, 8, 1}; C) scan dirty chunk pos-1.
        if (best < 0 && cb > 0) {
            int pos = cb >> 3;                       // in [1, 511]
            pos -= 64 * leading_clean7(sL64, pos, 64, thr);
            pos -= 8  * leading_clean7(sL8,  pos, 8,  thr);
            pos -=      leading_clean7(sL1,  pos, 1,  thr);
            if (pos > 0) {
                const int base = (pos - 1) * CH;     // guaranteed-dirty chunk
#pragma unroll
                for (int k = 0; k < CH; k++)
                    if (sn[base + k] < thr) best = base + k;
            }
        }

        out[(size_t)b * S_LEN + t] = best >= 0 ? (float)(t - best) : 0.0f;
    }
}

// ---------------------------------------------------------------------------
// Launch: single fused kernel, 128 blocks x 512 threads.
// ---------------------------------------------------------------------------
extern "C" void kernel_launch(void* const* d_in, const int* in_sizes, int n_in,
                              void* d_out, int out_size) {
    const float* x = (const float*)d_in[0];
    float* out = (float*)d_out;
    fused_kernel<<<NB, NT>>>(x, out);
}